// round 1
// baseline (speedup 1.0000x reference)
#include <cuda_runtime.h>
#include <cuda_bf16.h>

#define N_NODES 50000
#define N_EDGES 600000
#define DIM 128
#define EPS 1e-5f

// ---------------- scratch (device globals; no allocation allowed) ----------------
__device__ __align__(16) float g_s[N_NODES * DIM];   // projected support s = ttx@W+b'
__device__ __align__(16) float g_h[N_NODES * DIM];   // layer-1 output (GN'd)
__device__ int   g_cnt[N_NODES];
__device__ int   g_rowptr[N_NODES + 1];
__device__ int   g_cursor[N_NODES];
__device__ int   g_esrc[N_EDGES];
__device__ float g_ew[N_EDGES];

// ---------------- CSR build ----------------
__global__ void hist_kernel(const int* __restrict__ tgt, int* __restrict__ cnt, int e)
{
    int i = blockIdx.x * blockDim.x + threadIdx.x;
    if (i < e) atomicAdd(&cnt[tgt[i]], 1);
}

// single-block exclusive scan over cnt[n] -> rowptr / cursor; rowptr[n] = total
__global__ void scan_kernel(const int* __restrict__ cnt, int* __restrict__ rowptr,
                            int* __restrict__ cursor, int n)
{
    __shared__ int warp_sums[32];
    __shared__ int s_carry;
    int tid  = threadIdx.x;
    int lane = tid & 31;
    int wid  = tid >> 5;
    if (tid == 0) s_carry = 0;
    __syncthreads();

    for (int base = 0; base < n; base += blockDim.x) {
        int i = base + tid;
        int v = (i < n) ? cnt[i] : 0;
        // warp inclusive scan
        int x = v;
        #pragma unroll
        for (int off = 1; off < 32; off <<= 1) {
            int y = __shfl_up_sync(0xffffffffu, x, off);
            if (lane >= off) x += y;
        }
        if (lane == 31) warp_sums[wid] = x;
        __syncthreads();
        if (wid == 0) {
            int ws = warp_sums[lane];
            #pragma unroll
            for (int off = 1; off < 32; off <<= 1) {
                int y = __shfl_up_sync(0xffffffffu, ws, off);
                if (lane >= off) ws += y;
            }
            warp_sums[lane] = ws;   // inclusive warp totals
        }
        __syncthreads();
        int warp_off = (wid > 0) ? warp_sums[wid - 1] : 0;
        int incl = x + warp_off;
        int excl = incl - v;
        int carry = s_carry;
        if (i < n) {
            rowptr[i] = carry + excl;
            cursor[i] = carry + excl;
        }
        __syncthreads();
        if (tid == blockDim.x - 1) s_carry = carry + incl;
        __syncthreads();
    }
    if (tid == 0) rowptr[n] = s_carry;
}

__global__ void scatter_kernel(const int* __restrict__ src, const int* __restrict__ tgt,
                               const float* __restrict__ ew, int* __restrict__ cursor,
                               int* __restrict__ esrc, float* __restrict__ ewo, int e)
{
    int i = blockIdx.x * blockDim.x + threadIdx.x;
    if (i < e) {
        int t = tgt[i];
        int pos = atomicAdd(&cursor[t], 1);
        esrc[pos] = src[i];
        ewo[pos]  = ew[i];
    }
}

// ---------------- GEMM: S[n,128] = X[n,128] @ Wsub[128,128] + (b + t*Wrow0) ----------------
// Wsub = W + 128 (rows 1..128 of the [129,128] matrix); Wrow0 = W (row 0).
#define BM 64
#define BK 32
__global__ __launch_bounds__(256) void gemm_kernel(
    const float* __restrict__ X, const float* __restrict__ Wsub,
    const float* __restrict__ Wrow0, const float* __restrict__ bvec,
    const float* __restrict__ tptr, float* __restrict__ S, int n)
{
    __shared__ float xs[BM][BK + 1];   // +1 pad, scalar broadcast reads anyway
    __shared__ float ws[BK][DIM];

    int tid = threadIdx.x;
    int block_row = blockIdx.x * BM;
    int c4 = (tid & 31) * 4;   // column base (0..124)
    int r0 = (tid >> 5) * 8;   // row base within tile (0..56)

    float acc[8][4];
    #pragma unroll
    for (int r = 0; r < 8; r++)
        #pragma unroll
        for (int j = 0; j < 4; j++) acc[r][j] = 0.f;

    for (int k0 = 0; k0 < DIM; k0 += BK) {
        // load W tile: 32 x 128 floats = 1024 float4, 4 per thread
        #pragma unroll
        for (int i = tid; i < BK * DIM / 4; i += 256) {
            int kk = i >> 5;          // 32 float4 per row
            int cc = (i & 31) * 4;
            float4 wv = *(const float4*)(Wsub + (k0 + kk) * DIM + cc);
            *(float4*)&ws[kk][cc] = wv;
        }
        // load X tile: 64 x 32 floats = 512 float4, 2 per thread
        #pragma unroll
        for (int i = tid; i < BM * BK / 4; i += 256) {
            int rr  = i >> 3;         // 8 float4 per row
            int cc4 = (i & 7) * 4;
            int grow = block_row + rr;
            float4 xv = make_float4(0.f, 0.f, 0.f, 0.f);
            if (grow < n) xv = *(const float4*)(X + grow * DIM + k0 + cc4);
            xs[rr][cc4 + 0] = xv.x;
            xs[rr][cc4 + 1] = xv.y;
            xs[rr][cc4 + 2] = xv.z;
            xs[rr][cc4 + 3] = xv.w;
        }
        __syncthreads();

        #pragma unroll
        for (int kk = 0; kk < BK; kk++) {
            float4 wv = *(const float4*)&ws[kk][c4];
            float xr[8];
            #pragma unroll
            for (int r = 0; r < 8; r++) xr[r] = xs[r0 + r][kk];
            #pragma unroll
            for (int r = 0; r < 8; r++) {
                acc[r][0] = fmaf(xr[r], wv.x, acc[r][0]);
                acc[r][1] = fmaf(xr[r], wv.y, acc[r][1]);
                acc[r][2] = fmaf(xr[r], wv.z, acc[r][2]);
                acc[r][3] = fmaf(xr[r], wv.w, acc[r][3]);
            }
        }
        __syncthreads();
    }

    float tval = *tptr;
    float4 b0 = *(const float4*)(bvec + c4);
    float4 w0 = *(const float4*)(Wrow0 + c4);
    float bb[4];
    bb[0] = fmaf(tval, w0.x, b0.x);
    bb[1] = fmaf(tval, w0.y, b0.y);
    bb[2] = fmaf(tval, w0.z, b0.z);
    bb[3] = fmaf(tval, w0.w, b0.w);

    #pragma unroll
    for (int r = 0; r < 8; r++) {
        int grow = block_row + r0 + r;
        if (grow < n) {
            float4 o;
            o.x = acc[r][0] + bb[0];
            o.y = acc[r][1] + bb[1];
            o.z = acc[r][2] + bb[2];
            o.w = acc[r][3] + bb[3];
            *(float4*)(S + grow * DIM + c4) = o;
        }
    }
}

// ---------------- aggregation + ReLU + GroupNorm (group size 4 == one lane) ----------------
__global__ __launch_bounds__(256) void agg_gn_kernel(
    const float* __restrict__ S, const int* __restrict__ rowptr,
    const int* __restrict__ esrc, const float* __restrict__ ew,
    const float* __restrict__ gamma, const float* __restrict__ beta,
    float* __restrict__ out, int n)
{
    int warp = (blockIdx.x * blockDim.x + threadIdx.x) >> 5;
    int lane = threadIdx.x & 31;
    if (warp >= n) return;

    int beg = rowptr[warp];
    int end = rowptr[warp + 1];

    float ax = 0.f, ay = 0.f, az = 0.f, aw = 0.f;
    for (int j = beg; j < end; j++) {
        int s  = esrc[j];
        float w = ew[j];
        float4 v = *(const float4*)(S + s * DIM + lane * 4);
        ax = fmaf(w, v.x, ax);
        ay = fmaf(w, v.y, ay);
        az = fmaf(w, v.z, az);
        aw = fmaf(w, v.w, aw);
    }
    // ReLU
    ax = fmaxf(ax, 0.f); ay = fmaxf(ay, 0.f);
    az = fmaxf(az, 0.f); aw = fmaxf(aw, 0.f);
    // GroupNorm over this lane's 4 channels
    float mu = (ax + ay + az + aw) * 0.25f;
    float d0 = ax - mu, d1 = ay - mu, d2 = az - mu, d3 = aw - mu;
    float var = (d0 * d0 + d1 * d1 + d2 * d2 + d3 * d3) * 0.25f;
    float inv = rsqrtf(var + EPS);
    float4 g = *(const float4*)(gamma + lane * 4);
    float4 b = *(const float4*)(beta  + lane * 4);
    float4 o;
    o.x = fmaf(d0 * inv, g.x, b.x);
    o.y = fmaf(d1 * inv, g.y, b.y);
    o.z = fmaf(d2 * inv, g.z, b.z);
    o.w = fmaf(d3 * inv, g.w, b.w);
    *(float4*)(out + warp * DIM + lane * 4) = o;
}

// ---------------- launch ----------------
extern "C" void kernel_launch(void* const* d_in, const int* in_sizes, int n_in,
                              void* d_out, int out_size)
{
    const float* t      = (const float*)d_in[0];
    const float* x      = (const float*)d_in[1];
    const int*   src    = (const int*)  d_in[2];
    const int*   tgt    = (const int*)  d_in[3];
    const float* edge_w = (const float*)d_in[4];
    const float* W1     = (const float*)d_in[5];
    const float* b1     = (const float*)d_in[6];
    const float* W2     = (const float*)d_in[7];
    const float* b2     = (const float*)d_in[8];
    const float* gamma1 = (const float*)d_in[9];
    const float* beta1  = (const float*)d_in[10];
    const float* gamma2 = (const float*)d_in[11];
    const float* beta2  = (const float*)d_in[12];
    float* out = (float*)d_out;

    float* s_buf;  cudaGetSymbolAddress((void**)&s_buf,  g_s);
    float* h_buf;  cudaGetSymbolAddress((void**)&h_buf,  g_h);
    int*   cnt;    cudaGetSymbolAddress((void**)&cnt,    g_cnt);
    int*   rowptr; cudaGetSymbolAddress((void**)&rowptr, g_rowptr);
    int*   cursor; cudaGetSymbolAddress((void**)&cursor, g_cursor);
    int*   esrc;   cudaGetSymbolAddress((void**)&esrc,   g_esrc);
    float* ewo;    cudaGetSymbolAddress((void**)&ewo,    g_ew);

    // ---- CSR build (once; reused by both layers) ----
    cudaMemsetAsync(cnt, 0, N_NODES * sizeof(int));
    hist_kernel<<<(N_EDGES + 255) / 256, 256>>>(tgt, cnt, N_EDGES);
    scan_kernel<<<1, 1024>>>(cnt, rowptr, cursor, N_NODES);
    scatter_kernel<<<(N_EDGES + 255) / 256, 256>>>(src, tgt, edge_w, cursor, esrc, ewo, N_EDGES);

    int gemm_blocks = (N_NODES + BM - 1) / BM;
    int agg_blocks  = (N_NODES + 7) / 8;   // 8 warps per 256-thread block

    // ---- layer 1 ----
    gemm_kernel<<<gemm_blocks, 256>>>(x, W1 + DIM, W1, b1, t, s_buf, N_NODES);
    agg_gn_kernel<<<agg_blocks, 256>>>(s_buf, rowptr, esrc, ewo, gamma1, beta1, h_buf, N_NODES);

    // ---- layer 2 ----
    gemm_kernel<<<gemm_blocks, 256>>>(h_buf, W2 + DIM, W2, b2, t, s_buf, N_NODES);
    agg_gn_kernel<<<agg_blocks, 256>>>(s_buf, rowptr, esrc, ewo, gamma2, beta2, out, N_NODES);
}